// round 3
// baseline (speedup 1.0000x reference)
#include <cuda_runtime.h>
#include <cuda_bf16.h>
#include <math.h>

typedef unsigned long long ull;
#define DEVI __device__ __forceinline__

// ---------------- packed f32x2 FFMA2 (sm_103a) ----------------
DEVI void fma2(ull& d, ull a, ull b) {
    asm("fma.rn.f32x2 %0, %1, %2, %0;" : "+l"(d) : "l"(a), "l"(b));
}
DEVI float psum(ull a) {
    float x, y;
    asm("mov.b64 {%0,%1}, %2;" : "=f"(x), "=f"(y) : "l"(a));
    return x + y;
}

// ---------------- activations (precise) ----------------
DEVI float sigm(float x)  { return 1.f / (1.f + expf(-x)); }
DEVI float siluf(float x) { return x / (1.f + expf(-x)); }
DEVI float softpl(float x){ return fmaxf(x, 0.f) + log1pf(expf(-fabsf(x))); }
DEVI float geluf(float x) { return 0.5f * x * (1.f + erff(x * 0.70710678f)); }

// ---------------- problem constants ----------------
#define NBLK 128
#define TB   64
#define NTHR 512

// output element offsets
#define SCAL_OFF 0ull
#define K_OFF    73728ull
#define KI_OFF   81920ull
#define ST0_OFF  90112ull
#define ST1_OFF  67198976ull

// smem layout (floats)
#define HS_OFF   0                          // hs  [64][128]
#define XS_OFF   (HS_OFF + 64*128)          // xss [64][256] (x tile in input stage, stride 62)
#define WS0_OFF  (XS_OFF + 64*256)          // ws0 [64][132] (w_in in input stage, stride 62)
#define WS1_OFF  (WS0_OFF + 64*132)         // ws1 [64][132]
#define TS_OFF   (WS1_OFF + 64*132)         // ts  [64][132] pre-LN scratch
#define BC_OFF   (TS_OFF + 64*132)          // bcs [64][68]  (B|C, later gelu(t1))
#define DTB_OFF  (BC_OFF + 64*68)           // dtB [64][32]
#define YA_OFF   (DTB_OFF + 64*32)          // ya  [64]
#define SMEM_FLOATS (YA_OFF + 64)
#define SMEM_BYTES  (SMEM_FLOATS * 4)       // 225,536 B

// ---- 64x64 output tile, K=128, f32x2 GEMM, 512 threads (2x4 per thread) ----
// A: smem stride lda. W: smem stride 132. Accumulates into vals.
DEVI void gemm64(const float* __restrict__ a, int lda, const float* __restrict__ w,
                 float vals[2][4], int tr, int tc) {
    ull acc[2][4];
    #pragma unroll
    for (int i = 0; i < 2; i++)
        #pragma unroll
        for (int j = 0; j < 4; j++) acc[i][j] = 0ull;
    #pragma unroll 4
    for (int k = 0; k < 128; k += 4) {
        ulonglong2 av[2], bv[4];
        #pragma unroll
        for (int i = 0; i < 2; i++) av[i] = *(const ulonglong2*)(a + (tr + 32*i)*lda + k);
        #pragma unroll
        for (int j = 0; j < 4; j++) bv[j] = *(const ulonglong2*)(w + (tc + 16*j)*132 + k);
        #pragma unroll
        for (int i = 0; i < 2; i++)
            #pragma unroll
            for (int j = 0; j < 4; j++) {
                fma2(acc[i][j], av[i].x, bv[j].x);
                fma2(acc[i][j], av[i].y, bv[j].y);
            }
    }
    #pragma unroll
    for (int i = 0; i < 2; i++)
        #pragma unroll
        for (int j = 0; j < 4; j++) vals[i][j] += psum(acc[i][j]);
}

// split weight-slab load: global->regs (issue early), regs->smem (after gemm)
DEVI void ldg_ws(float4 v[4], const float* __restrict__ g, int gld) {
    #pragma unroll
    for (int t = 0; t < 4; t++) {
        int idx = threadIdx.x + t * NTHR;   // 0..2047
        int r = idx >> 5, kq = idx & 31;
        v[t] = __ldg((const float4*)(g + r*gld + kq*4));
    }
}
DEVI void sts_ws(float* ws, const float4 v[4]) {
    #pragma unroll
    for (int t = 0; t < 4; t++) {
        int idx = threadIdx.x + t * NTHR;
        int r = idx >> 5, kq = idx & 31;
        *(float4*)(ws + r*132 + kq*4) = v[t];
    }
}

// per-row LayerNorm over 128 cols; warp w owns rows [4w, 4w+4). No internal syncs.
DEVI void do_ln(float* hs, const float* src, int lds,
                const float* __restrict__ g, const float* __restrict__ b, bool addres) {
    int w = threadIdx.x >> 5, lane = threadIdx.x & 31;
    float4 gg = *(const float4*)(g + lane*4);
    float4 bb = *(const float4*)(b + lane*4);
    for (int r = w*4; r < w*4 + 4; r++) {
        float4 v = *(const float4*)(src + r*lds + lane*4);
        if (addres) {
            float4 h = *(const float4*)(hs + r*128 + lane*4);
            v.x += h.x; v.y += h.y; v.z += h.z; v.w += h.w;
        }
        float s = v.x + v.y + v.z + v.w;
        float q = v.x*v.x + v.y*v.y + v.z*v.z + v.w*v.w;
        #pragma unroll
        for (int o = 16; o > 0; o >>= 1) {
            s += __shfl_xor_sync(0xffffffffu, s, o);
            q += __shfl_xor_sync(0xffffffffu, q, o);
        }
        float m   = s * (1.f/128.f);
        float inv = rsqrtf(fmaxf(q * (1.f/128.f) - m*m, 0.f) + 1e-5f);
        float4 o4;
        o4.x = (v.x - m)*inv*gg.x + bb.x;
        o4.y = (v.y - m)*inv*gg.y + bb.y;
        o4.z = (v.z - m)*inv*gg.z + bb.z;
        o4.w = (v.w - m)*inv*gg.w + bb.w;
        *(float4*)(hs + r*128 + lane*4) = o4;
    }
}

__global__ void __launch_bounds__(NTHR, 1) fused_kernel(
    const float* __restrict__ x,      const float* __restrict__ w_in,
    const float* __restrict__ b_in,   const float* __restrict__ ln_in_g,
    const float* __restrict__ ln_in_b,
    const float* __restrict__ in_w0,  const float* __restrict__ Dp0,
    const float* __restrict__ out_w0, const float* __restrict__ ln_g0,
    const float* __restrict__ ln_b0,
    const float* __restrict__ in_w1,  const float* __restrict__ Dp1,
    const float* __restrict__ out_w1, const float* __restrict__ ln_g1,
    const float* __restrict__ ln_b1,
    const float* __restrict__ fn_g,   const float* __restrict__ fn_b,
    const float* __restrict__ sh_w1,  const float* __restrict__ sh_b1,
    const float* __restrict__ sh_w2,  const float* __restrict__ sh_b2,
    const float* __restrict__ k_w,    const float* __restrict__ k_b,
    const float* __restrict__ ki_w,   const float* __restrict__ ki_b,
    float* __restrict__ outp)
{
    extern __shared__ float sm[];
    float* hs   = sm + HS_OFF;
    float* xss  = sm + XS_OFF;
    float* ws0  = sm + WS0_OFF;
    float* ws1  = sm + WS1_OFF;
    float* ts   = sm + TS_OFF;
    float* bcs  = sm + BC_OFF;
    float* dtBs = sm + DTB_OFF;
    float* yav  = sm + YA_OFF;

    const int tid = threadIdx.x;
    const int tr = tid >> 4, tc = tid & 15;            // 32x16 thread grid
    const int rowbase = blockIdx.x * TB;

    // ============ input stage: h = LN(x @ w_in^T + b_in) ============
    for (int idx = tid; idx < 64*58; idx += NTHR) {
        int r = idx / 58, k = idx - r*58;
        xss[r*62 + k] = x[(size_t)(rowbase + r)*58 + k];
    }
    for (int idx = tid; idx < 128*58; idx += NTHR) {
        int r = idx / 58, k = idx - r*58;
        ws0[r*62 + k] = w_in[idx];
    }
    __syncthreads();
    {
        float4 pf[4];
        ldg_ws(pf, in_w0 + 512*128, 128);              // prefetch L0 B|C slab
        #pragma unroll
        for (int ch2 = 0; ch2 < 2; ch2++) {
            ull acc[2][4];
            #pragma unroll
            for (int i = 0; i < 2; i++)
                #pragma unroll
                for (int j = 0; j < 4; j++) acc[i][j] = 0ull;
            #pragma unroll 1
            for (int k = 0; k < 58; k += 2) {
                ull a0 = *(const ull*)(xss + tr*62 + k);
                ull a1 = *(const ull*)(xss + (tr+32)*62 + k);
                #pragma unroll
                for (int j = 0; j < 4; j++) {
                    ull b = *(const ull*)(ws0 + (ch2*64 + tc + 16*j)*62 + k);
                    fma2(acc[0][j], a0, b);
                    fma2(acc[1][j], a1, b);
                }
            }
            #pragma unroll
            for (int i = 0; i < 2; i++)
                #pragma unroll
                for (int j = 0; j < 4; j++) {
                    int c = ch2*64 + tc + 16*j;
                    ts[(tr + 32*i)*132 + c] = psum(acc[i][j]) + __ldg(b_in + c);
                }
        }
        sts_ws(ws1, pf);
        __syncthreads();
    }
    do_ln(hs, ts, 132, ln_in_g, ln_in_b, false);
    __syncthreads();

    float* wc = ws1;   // current slab (holds L0 B|C)
    float* wn = ws0;   // next slab buffer

    // ============ two mamba layers ============
    const float* in_w_l[2]  = {in_w0, in_w1};
    const float* Dp_l[2]    = {Dp0, Dp1};
    const float* out_w_l[2] = {out_w0, out_w1};
    const float* g_l[2]     = {ln_g0, ln_g1};
    const float* b_l[2]     = {ln_b0, ln_b1};
    const ull    soff_l[2]  = {ST0_OFF, ST1_OFF};

    for (int L = 0; L < 2; L++) {
        const float* in_w  = in_w_l[L];
        const float* Dp    = Dp_l[L];
        const float* out_w = out_w_l[L];
        const ull    soff  = soff_l[L];
        const float* nxt_after = (L == 0) ? (in_w1 + 512*128) : sh_w1;

        // ---- B|C phase (proj cols 512..575) ----
        {
            float4 pf[4];
            ldg_ws(pf, in_w + 256*128, 128);           // prefetch xs0
            float vals[2][4] = {};
            gemm64(hs, 128, wc, vals, tr, tc);
            #pragma unroll
            for (int i = 0; i < 2; i++)
                #pragma unroll
                for (int j = 0; j < 4; j++)
                    bcs[(tr + 32*i)*68 + tc + 16*j] = vals[i][j];
            sts_ws(wn, pf);
            __syncthreads();
            { float* t = wc; wc = wn; wn = t; }
        }

        // ---- per-row scalars: dt (col 576), bc = B·C, dtB, ya ----
        if (tid < 64) {
            const float* wdt = in_w + 576*128;
            float acc = 0.f;
            #pragma unroll 4
            for (int kk = 0; kk < 128; kk++) {
                int k = (kk + tid) & 127;              // rotated: conflict-free
                acc += hs[tid*128 + k] * __ldg(wdt + k);
            }
            float dt = softpl(acc);
            float bc = 0.f;
            #pragma unroll
            for (int ss = 0; ss < 32; ss++) {
                int s = (ss + tid) & 31;
                float Bv = bcs[tid*68 + s];
                bc += Bv * bcs[tid*68 + 32 + s];
                dtBs[tid*32 + s] = dt * Bv;
            }
            yav[tid] = dt * bc;
        }

        // ---- x_ssm chunks (proj cols 256..511) + streaming state writes ----
        for (int sub = 0; sub < 4; sub++) {
            const float* nx = (sub < 3) ? (in_w + (256 + 64*(sub+1))*128) : in_w; // z0 next
            float4 pf[4];
            ldg_ws(pf, nx, 128);
            float vals[2][4] = {};
            gemm64(hs, 128, wc, vals, tr, tc);
            #pragma unroll
            for (int i = 0; i < 2; i++)
                #pragma unroll
                for (int j = 0; j < 4; j++)
                    xss[(tr + 32*i)*256 + sub*64 + tc + 16*j] = siluf(vals[i][j]);
            sts_ws(wn, pf);
            __syncthreads();
            { float* t = wc; wc = wn; wn = t; }

            // state[b, d, s] = silu(x_ssm)[b,d] * dtB[b,s] — coalesced .cs float4
            {
                int r = tid >> 3, sq = tid & 7;
                float4 db = *(const float4*)(dtBs + r*32 + sq*4);
                float* p = outp + soff
                         + ((ull)(rowbase + r)*256ull + (ull)(sub*64))*32ull + (ull)(sq*4);
                const float* xrow = xss + r*256 + sub*64;
                #pragma unroll 4
                for (int d = 0; d < 64; d++) {
                    float xv = xrow[d];
                    float4 v; v.x = xv*db.x; v.y = xv*db.y; v.z = xv*db.z; v.w = xv*db.w;
                    __stcs((float4*)p, v);
                    p += 32;
                }
            }
        }

        // ---- z chunks (proj cols 0..255): u = silu(z)*x_ssm*(ya+Dp) in-place ----
        for (int sub = 0; sub < 4; sub++) {
            const float* nx; int ngld;
            if (sub < 3) { nx = in_w + 64*(sub+1)*128; ngld = 128; }
            else         { nx = out_w;                 ngld = 256; }
            float4 pf[4];
            ldg_ws(pf, nx, ngld);
            float vals[2][4] = {};
            gemm64(hs, 128, wc, vals, tr, tc);
            #pragma unroll
            for (int i = 0; i < 2; i++)
                #pragma unroll
                for (int j = 0; j < 4; j++) {
                    int r = tr + 32*i, c = sub*64 + tc + 16*j;
                    float xv = xss[r*256 + c];
                    xss[r*256 + c] = siluf(vals[i][j]) * xv * (yav[r] + __ldg(Dp + c));
                }
            sts_ws(wn, pf);
            __syncthreads();
            { float* t = wc; wc = wn; wn = t; }
        }

        // ---- out GEMM: ts = u @ out_w^T (128 cols, K=256, 2x2 slabs) ----
        for (int ch = 0; ch < 2; ch++) {
            float vals[2][4] = {};
            for (int kh = 0; kh < 2; kh++) {
                int sidx = ch*2 + kh + 1;
                const float* nx; int ngld;
                if (sidx < 4) { nx = out_w + (size_t)(sidx >> 1)*64*256 + (sidx & 1)*128; ngld = 256; }
                else          { nx = nxt_after; ngld = 128; }
                float4 pf[4];
                ldg_ws(pf, nx, ngld);
                gemm64(xss + kh*128, 256, wc, vals, tr, tc);
                sts_ws(wn, pf);
                __syncthreads();
                { float* t = wc; wc = wn; wn = t; }
            }
            #pragma unroll
            for (int i = 0; i < 2; i++)
                #pragma unroll
                for (int j = 0; j < 4; j++)
                    ts[(tr + 32*i)*132 + ch*64 + tc + 16*j] = vals[i][j];
        }
        __syncthreads();
        do_ln(hs, ts, 132, g_l[L], b_l[L], true);      // h = LN(h + out)
        __syncthreads();
    }

    // ============ final LN + heads ============
    do_ln(hs, hs, 128, fn_g, fn_b, false);
    __syncthreads();

    // t1 = gelu(h @ sh_w1^T + sh_b1) -> bcs (stride 68); sh_w1 already in wc
    {
        float vals[2][4] = {};
        gemm64(hs, 128, wc, vals, tr, tc);
        #pragma unroll
        for (int i = 0; i < 2; i++)
            #pragma unroll
            for (int j = 0; j < 4; j++) {
                int c = tc + 16*j;
                bcs[(tr + 32*i)*68 + c] = geluf(vals[i][j] + __ldg(sh_b1 + c));
            }
    }
    __syncthreads();

    // scaling = softplus(t1 @ sh_w2^T + sh_b2)  (9 cols)
    for (int idx = tid; idx < 64*9; idx += NTHR) {
        int r = idx / 9, c = idx - r*9;
        float acc = __ldg(sh_b2 + c);
        #pragma unroll 4
        for (int ss = 0; ss < 64; ss++) {
            int s = (ss + tid) & 63;
            acc += bcs[r*68 + s] * __ldg(sh_w2 + c*64 + s);
        }
        outp[SCAL_OFF + (ull)(rowbase + r)*9ull + c] = softpl(acc);
    }

    // K, K_internal (per-row dots over h)
    if (tid < 64) {
        float a0 = 0.f, a1 = 0.f;
        #pragma unroll 4
        for (int kk = 0; kk < 128; kk++) {
            int k = (kk + tid) & 127;
            float hv = hs[tid*128 + k];
            a0 += hv * __ldg(k_w + k);
            a1 += hv * __ldg(ki_w + k);
        }
        outp[K_OFF  + (ull)(rowbase + tid)] = sigm(a0 + __ldg(k_b));
        outp[KI_OFF + (ull)(rowbase + tid)] = sigm(a1 + __ldg(ki_b));
    }
}

extern "C" void kernel_launch(void* const* d_in, const int* in_sizes, int n_in,
                              void* d_out, int out_size) {
    (void)in_sizes; (void)n_in; (void)out_size;
    cudaFuncSetAttribute(fused_kernel, cudaFuncAttributeMaxDynamicSharedMemorySize, SMEM_BYTES);
    fused_kernel<<<NBLK, NTHR, SMEM_BYTES>>>(
        (const float*)d_in[0],  (const float*)d_in[1],  (const float*)d_in[2],
        (const float*)d_in[3],  (const float*)d_in[4],
        (const float*)d_in[5],  (const float*)d_in[7],  (const float*)d_in[8],
        (const float*)d_in[9],  (const float*)d_in[10],
        (const float*)d_in[11], (const float*)d_in[13], (const float*)d_in[14],
        (const float*)d_in[15], (const float*)d_in[16],
        (const float*)d_in[17], (const float*)d_in[18],
        (const float*)d_in[19], (const float*)d_in[20],
        (const float*)d_in[21], (const float*)d_in[22],
        (const float*)d_in[23], (const float*)d_in[24],
        (const float*)d_in[25], (const float*)d_in[26],
        (float*)d_out);
}

// round 4
// speedup vs baseline: 1.1660x; 1.1660x over previous
#include <cuda_runtime.h>
#include <cuda_bf16.h>
#include <math.h>

typedef unsigned long long ull;
#define DEVI __device__ __forceinline__

// ---------------- packed f32x2 FFMA2 (sm_103a) ----------------
DEVI void fma2(ull& d, ull a, ull b) {
    asm("fma.rn.f32x2 %0, %1, %2, %0;" : "+l"(d) : "l"(a), "l"(b));
}
DEVI float psum(ull a) {
    float x, y;
    asm("mov.b64 {%0,%1}, %2;" : "=f"(x), "=f"(y) : "l"(a));
    return x + y;
}

// ---------------- activations (precise) ----------------
DEVI float sigm(float x)  { return 1.f / (1.f + expf(-x)); }
DEVI float siluf(float x) { return x / (1.f + expf(-x)); }
DEVI float softpl(float x){ return fmaxf(x, 0.f) + log1pf(expf(-fabsf(x))); }
DEVI float geluf(float x) { return 0.5f * x * (1.f + erff(x * 0.70710678f)); }

// ---------------- problem constants ----------------
#define NBLK 256
#define TB   32
#define NTHR 256

// output element offsets
#define SCAL_OFF 0ull
#define K_OFF    73728ull
#define KI_OFF   81920ull
#define ST0_OFF  90112ull
#define ST1_OFF  67198976ull

// smem layout (floats) — total 113,792 B => 2 CTAs/SM
#define HS_OFF   0                          // hs  [32][132]
#define XS_OFF   (HS_OFF + 32*132)          // xss [32][260] (x tile in input stage, stride 62)
#define WS_OFF   (XS_OFF + 32*260)          // ws  [64][132] (w_in 128x62 in input stage)
#define TS_OFF   (WS_OFF + 64*132)          // ts  [32][132] pre-LN scratch
#define BC_OFF   (TS_OFF + 32*132)          // bcs [32][68]  (B|C, later gelu(t1))
#define DTB_OFF  (BC_OFF + 32*68)           // dtB [32][32]
#define YA_OFF   (DTB_OFF + 32*32)          // ya  [32]
#define SMEM_FLOATS (YA_OFF + 32)
#define SMEM_BYTES  (SMEM_FLOATS * 4)

// ---- 32x64 output tile, K=128. Warp tile 16x16; thread: 4 rows x 2 cols.
// A: smem stride lda (≡4 mod 32 words). W: smem stride 132. Accumulates into vals.
DEVI void gemm32(const float* __restrict__ a, int lda, const float* __restrict__ w,
                 float vals[4][2], int row0, int col0) {
    ull acc[4][2];
    #pragma unroll
    for (int i = 0; i < 4; i++)
        #pragma unroll
        for (int j = 0; j < 2; j++) acc[i][j] = 0ull;
    #pragma unroll 4
    for (int k = 0; k < 128; k += 4) {
        ulonglong2 av[4], bv[2];
        #pragma unroll
        for (int i = 0; i < 4; i++) av[i] = *(const ulonglong2*)(a + (row0 + 4*i)*lda + k);
        #pragma unroll
        for (int j = 0; j < 2; j++) bv[j] = *(const ulonglong2*)(w + (col0 + 8*j)*132 + k);
        #pragma unroll
        for (int i = 0; i < 4; i++)
            #pragma unroll
            for (int j = 0; j < 2; j++) {
                fma2(acc[i][j], av[i].x, bv[j].x);
                fma2(acc[i][j], av[i].y, bv[j].y);
            }
    }
    #pragma unroll
    for (int i = 0; i < 4; i++)
        #pragma unroll
        for (int j = 0; j < 2; j++) vals[i][j] += psum(acc[i][j]);
}

// split weight-slab load (64 rows x 128 cols): global->regs, later regs->smem
DEVI void ldg_ws(float4 v[8], const float* __restrict__ g, int gld) {
    #pragma unroll
    for (int t = 0; t < 8; t++) {
        int idx = threadIdx.x + t * NTHR;   // 0..2047
        int r = idx >> 5, kq = idx & 31;
        v[t] = __ldg((const float4*)(g + r*gld + kq*4));
    }
}
DEVI void sts_ws(float* ws, const float4 v[8]) {
    #pragma unroll
    for (int t = 0; t < 8; t++) {
        int idx = threadIdx.x + t * NTHR;
        int r = idx >> 5, kq = idx & 31;
        *(float4*)(ws + r*132 + kq*4) = v[t];
    }
}

// per-row LayerNorm over 128 cols; warp w owns rows [4w, 4w+4).
DEVI void do_ln(float* hs, const float* src, int lds,
                const float* __restrict__ g, const float* __restrict__ b, bool addres) {
    int w = threadIdx.x >> 5, lane = threadIdx.x & 31;
    float4 gg = *(const float4*)(g + lane*4);
    float4 bb = *(const float4*)(b + lane*4);
    for (int r = w*4; r < w*4 + 4; r++) {
        float4 v = *(const float4*)(src + r*lds + lane*4);
        if (addres) {
            float4 h = *(const float4*)(hs + r*132 + lane*4);
            v.x += h.x; v.y += h.y; v.z += h.z; v.w += h.w;
        }
        float s = v.x + v.y + v.z + v.w;
        float q = v.x*v.x + v.y*v.y + v.z*v.z + v.w*v.w;
        #pragma unroll
        for (int o = 16; o > 0; o >>= 1) {
            s += __shfl_xor_sync(0xffffffffu, s, o);
            q += __shfl_xor_sync(0xffffffffu, q, o);
        }
        float m   = s * (1.f/128.f);
        float inv = rsqrtf(fmaxf(q * (1.f/128.f) - m*m, 0.f) + 1e-5f);
        float4 o4;
        o4.x = (v.x - m)*inv*gg.x + bb.x;
        o4.y = (v.y - m)*inv*gg.y + bb.y;
        o4.z = (v.z - m)*inv*gg.z + bb.z;
        o4.w = (v.w - m)*inv*gg.w + bb.w;
        *(float4*)(hs + r*132 + lane*4) = o4;
    }
}

__global__ void __launch_bounds__(NTHR, 2) fused_kernel(
    const float* __restrict__ x,      const float* __restrict__ w_in,
    const float* __restrict__ b_in,   const float* __restrict__ ln_in_g,
    const float* __restrict__ ln_in_b,
    const float* __restrict__ in_w0,  const float* __restrict__ Dp0,
    const float* __restrict__ out_w0, const float* __restrict__ ln_g0,
    const float* __restrict__ ln_b0,
    const float* __restrict__ in_w1,  const float* __restrict__ Dp1,
    const float* __restrict__ out_w1, const float* __restrict__ ln_g1,
    const float* __restrict__ ln_b1,
    const float* __restrict__ fn_g,   const float* __restrict__ fn_b,
    const float* __restrict__ sh_w1,  const float* __restrict__ sh_b1,
    const float* __restrict__ sh_w2,  const float* __restrict__ sh_b2,
    const float* __restrict__ k_w,    const float* __restrict__ k_b,
    const float* __restrict__ ki_w,   const float* __restrict__ ki_b,
    float* __restrict__ outp)
{
    extern __shared__ float sm[];
    float* hs   = sm + HS_OFF;
    float* xss  = sm + XS_OFF;
    float* ws   = sm + WS_OFF;
    float* ts   = sm + TS_OFF;
    float* bcs  = sm + BC_OFF;
    float* dtBs = sm + DTB_OFF;
    float* yav  = sm + YA_OFF;

    const int tid  = threadIdx.x;
    const int wid  = tid >> 5, lane = tid & 31;
    const int wr   = wid & 1,  wc2  = wid >> 1;      // warp grid 2x4
    const int lr   = lane >> 3, lc  = lane & 7;      // lane grid 4x8
    const int row0 = wr*16 + lr;                     // rows row0 + 4i
    const int col0 = wc2*16 + lc;                    // cols col0 + 8j
    const int rowbase = blockIdx.x * TB;

    // ============ input stage: h = LN(x @ w_in^T + b_in) ============
    for (int idx = tid; idx < 32*58; idx += NTHR) {
        int r = idx / 58, k = idx - r*58;
        xss[r*62 + k] = x[(size_t)(rowbase + r)*58 + k];
    }
    for (int idx = tid; idx < 128*58; idx += NTHR) {
        int r = idx / 58, k = idx - r*58;
        ws[r*62 + k] = w_in[idx];
    }
    __syncthreads();
    {
        // out 32x128: cols c = wc2*32 + lc + 8j, j=0..3
        ull acc[4][4];
        #pragma unroll
        for (int i = 0; i < 4; i++)
            #pragma unroll
            for (int j = 0; j < 4; j++) acc[i][j] = 0ull;
        #pragma unroll 1
        for (int k = 0; k < 58; k += 2) {
            ull a[4], b[4];
            #pragma unroll
            for (int i = 0; i < 4; i++) a[i] = *(const ull*)(xss + (row0 + 4*i)*62 + k);
            #pragma unroll
            for (int j = 0; j < 4; j++) b[j] = *(const ull*)(ws + (wc2*32 + lc + 8*j)*62 + k);
            #pragma unroll
            for (int i = 0; i < 4; i++)
                #pragma unroll
                for (int j = 0; j < 4; j++) fma2(acc[i][j], a[i], b[j]);
        }
        #pragma unroll
        for (int i = 0; i < 4; i++)
            #pragma unroll
            for (int j = 0; j < 4; j++) {
                int c = wc2*32 + lc + 8*j;
                ts[(row0 + 4*i)*132 + c] = psum(acc[i][j]) + __ldg(b_in + c);
            }
    }
    __syncthreads();
    do_ln(hs, ts, 132, ln_in_g, ln_in_b, false);
    __syncthreads();

    // load L0 B/C slab plainly (no prefetch across the input stage)
    {
        float4 pf[8];
        ldg_ws(pf, in_w0 + 512*128, 128);
        sts_ws(ws, pf);
        __syncthreads();
    }

    // ============ two mamba layers ============
    const float* in_w_l[2]  = {in_w0, in_w1};
    const float* Dp_l[2]    = {Dp0, Dp1};
    const float* out_w_l[2] = {out_w0, out_w1};
    const float* g_l[2]     = {ln_g0, ln_g1};
    const float* b_l[2]     = {ln_b0, ln_b1};
    const ull    soff_l[2]  = {ST0_OFF, ST1_OFF};

    for (int L = 0; L < 2; L++) {
        const float* in_w  = in_w_l[L];
        const float* Dp    = Dp_l[L];
        const float* out_w = out_w_l[L];
        const ull    soff  = soff_l[L];
        const float* nxt_after = (L == 0) ? (in_w1 + 512*128) : sh_w1;

        // ---- B|C phase (proj cols 512..575) ----
        {
            float4 pf[8];
            ldg_ws(pf, in_w + 256*128, 128);           // prefetch xs0
            float vals[4][2] = {};
            gemm32(hs, 132, ws, vals, row0, col0);
            #pragma unroll
            for (int i = 0; i < 4; i++)
                #pragma unroll
                for (int j = 0; j < 2; j++)
                    bcs[(row0 + 4*i)*68 + col0 + 8*j] = vals[i][j];
            __syncthreads();
            sts_ws(ws, pf);
            __syncthreads();
        }

        // ---- per-row scalars: dt (col 576), bc = B·C, dtB, ya ----
        if (tid < 32) {
            const float* wdt = in_w + 576*128;
            float acc = 0.f;
            #pragma unroll 4
            for (int kk = 0; kk < 128; kk++) {
                int k = (kk + tid) & 127;              // rotated: conflict-free
                acc += hs[tid*132 + k] * __ldg(wdt + k);
            }
            float dt = softpl(acc);
            float bc = 0.f;
            #pragma unroll
            for (int ss = 0; ss < 32; ss++) {
                int s = (ss + tid) & 31;
                float Bv = bcs[tid*68 + s];
                bc += Bv * bcs[tid*68 + 32 + s];
                dtBs[tid*32 + s] = dt * Bv;
            }
            yav[tid] = dt * bc;
        }

        // ---- x_ssm chunks (proj cols 256..511) + streaming state writes ----
        for (int sub = 0; sub < 4; sub++) {
            const float* nx = (sub < 3) ? (in_w + (256 + 64*(sub+1))*128) : in_w; // z0 next
            float4 pf[8];
            ldg_ws(pf, nx, 128);
            float vals[4][2] = {};
            gemm32(hs, 132, ws, vals, row0, col0);
            #pragma unroll
            for (int i = 0; i < 4; i++)
                #pragma unroll
                for (int j = 0; j < 2; j++)
                    xss[(row0 + 4*i)*260 + sub*64 + col0 + 8*j] = siluf(vals[i][j]);
            __syncthreads();                           // xss + dtB ready for stores
            sts_ws(ws, pf);

            // state[b, d, s] = silu(x_ssm)[b,d] * dtB[b,s] — coalesced .cs float4
            {
                int r = tid >> 3, sq = tid & 7;
                float4 db = *(const float4*)(dtBs + r*32 + sq*4);
                float* p = outp + soff
                         + ((ull)(rowbase + r)*256ull + (ull)(sub*64))*32ull + (ull)(sq*4);
                const float* xrow = xss + r*260 + sub*64;
                #pragma unroll 4
                for (int d = 0; d < 64; d++) {
                    float xv = xrow[d];
                    float4 v; v.x = xv*db.x; v.y = xv*db.y; v.z = xv*db.z; v.w = xv*db.w;
                    __stcs((float4*)p, v);
                    p += 32;
                }
            }
            __syncthreads();
        }

        // ---- z chunks (proj cols 0..255): u = silu(z)*x_ssm*(ya+Dp) in-place ----
        for (int sub = 0; sub < 4; sub++) {
            const float* nx; int ngld;
            if (sub < 3) { nx = in_w + 64*(sub+1)*128; ngld = 128; }
            else         { nx = out_w;                 ngld = 256; }
            float4 pf[8];
            ldg_ws(pf, nx, ngld);
            float vals[4][2] = {};
            gemm32(hs, 132, ws, vals, row0, col0);
            #pragma unroll
            for (int i = 0; i < 4; i++)
                #pragma unroll
                for (int j = 0; j < 2; j++) {
                    int r = row0 + 4*i, c = sub*64 + col0 + 8*j;
                    float xv = xss[r*260 + c];
                    xss[r*260 + c] = siluf(vals[i][j]) * xv * (yav[r] + __ldg(Dp + c));
                }
            __syncthreads();
            sts_ws(ws, pf);
            __syncthreads();
        }

        // ---- out GEMM: ts = u @ out_w^T (128 cols, K=256, 2x2 slabs) ----
        for (int ch = 0; ch < 2; ch++) {
            float vals[4][2] = {};
            for (int kh = 0; kh < 2; kh++) {
                int sidx = ch*2 + kh + 1;
                const float* nx; int ngld;
                if (sidx < 4) { nx = out_w + (size_t)(sidx >> 1)*64*256 + (sidx & 1)*128; ngld = 256; }
                else          { nx = nxt_after; ngld = 128; }
                float4 pf[8];
                ldg_ws(pf, nx, ngld);
                gemm32(xss + kh*128, 260, ws, vals, row0, col0);
                __syncthreads();
                sts_ws(ws, pf);
                __syncthreads();
            }
            #pragma unroll
            for (int i = 0; i < 4; i++)
                #pragma unroll
                for (int j = 0; j < 2; j++)
                    ts[(row0 + 4*i)*132 + ch*64 + col0 + 8*j] = vals[i][j];
        }
        __syncthreads();
        do_ln(hs, ts, 132, g_l[L], b_l[L], true);      // h = LN(h + out)
        __syncthreads();
    }

    // ============ final LN + heads ============
    do_ln(hs, hs, 132, fn_g, fn_b, false);
    __syncthreads();

    // t1 = gelu(h @ sh_w1^T + sh_b1) -> bcs (stride 68); sh_w1 already in ws
    {
        float vals[4][2] = {};
        gemm32(hs, 132, ws, vals, row0, col0);
        #pragma unroll
        for (int i = 0; i < 4; i++)
            #pragma unroll
            for (int j = 0; j < 2; j++) {
                int c = col0 + 8*j;
                bcs[(row0 + 4*i)*68 + c] = geluf(vals[i][j] + __ldg(sh_b1 + c));
            }
    }
    __syncthreads();

    // scaling = softplus(t1 @ sh_w2^T + sh_b2)  (9 cols)
    for (int idx = tid; idx < 32*9; idx += NTHR) {
        int r = idx / 9, c = idx - r*9;
        float acc = __ldg(sh_b2 + c);
        #pragma unroll 4
        for (int ss = 0; ss < 64; ss++) {
            int s = (ss + tid) & 63;
            acc += bcs[r*68 + s] * __ldg(sh_w2 + c*64 + s);
        }
        outp[SCAL_OFF + (ull)(rowbase + r)*9ull + c] = softpl(acc);
    }

    // K, K_internal (per-row dots over h)
    if (tid < 32) {
        float a0 = 0.f, a1 = 0.f;
        #pragma unroll 4
        for (int kk = 0; kk < 128; kk++) {
            int k = (kk + tid) & 127;
            float hv = hs[tid*132 + k];
            a0 += hv * __ldg(k_w + k);
            a1 += hv * __ldg(ki_w + k);
        }
        outp[K_OFF  + (ull)(rowbase + tid)] = sigm(a0 + __ldg(k_b));
        outp[KI_OFF + (ull)(rowbase + tid)] = sigm(a1 + __ldg(ki_b));
    }
}

extern "C" void kernel_launch(void* const* d_in, const int* in_sizes, int n_in,
                              void* d_out, int out_size) {
    (void)in_sizes; (void)n_in; (void)out_size;
    cudaFuncSetAttribute(fused_kernel, cudaFuncAttributeMaxDynamicSharedMemorySize, SMEM_BYTES);
    fused_kernel<<<NBLK, NTHR, SMEM_BYTES>>>(
        (const float*)d_in[0],  (const float*)d_in[1],  (const float*)d_in[2],
        (const float*)d_in[3],  (const float*)d_in[4],
        (const float*)d_in[5],  (const float*)d_in[7],  (const float*)d_in[8],
        (const float*)d_in[9],  (const float*)d_in[10],
        (const float*)d_in[11], (const float*)d_in[13], (const float*)d_in[14],
        (const float*)d_in[15], (const float*)d_in[16],
        (const float*)d_in[17], (const float*)d_in[18],
        (const float*)d_in[19], (const float*)d_in[20],
        (const float*)d_in[21], (const float*)d_in[22],
        (const float*)d_in[23], (const float*)d_in[24],
        (const float*)d_in[25], (const float*)d_in[26],
        (float*)d_out);
}

// round 5
// speedup vs baseline: 1.2567x; 1.0778x over previous
#include <cuda_runtime.h>
#include <cuda_bf16.h>
#include <math.h>

typedef unsigned long long ull;
#define DEVI __device__ __forceinline__

// ---------------- packed f32x2 FFMA2 (sm_103a) ----------------
DEVI void fma2(ull& d, ull a, ull b) {
    asm("fma.rn.f32x2 %0, %1, %2, %0;" : "+l"(d) : "l"(a), "l"(b));
}
DEVI float psum(ull a) {
    float x, y;
    asm("mov.b64 {%0,%1}, %2;" : "=f"(x), "=f"(y) : "l"(a));
    return x + y;
}

// ---------------- activations (precise) ----------------
DEVI float sigm(float x)  { return 1.f / (1.f + expf(-x)); }
DEVI float siluf(float x) { return x / (1.f + expf(-x)); }
DEVI float softpl(float x){ return fmaxf(x, 0.f) + log1pf(expf(-fabsf(x))); }
DEVI float geluf(float x) { return 0.5f * x * (1.f + erff(x * 0.70710678f)); }

// ---------------- problem constants ----------------
#define NBLK 256
#define TB   32
#define NTHR 256

// output element offsets
#define SCAL_OFF 0ull
#define K_OFF    73728ull
#define KI_OFF   81920ull
#define ST0_OFF  90112ull
#define ST1_OFF  67198976ull

// smem layout (floats) — 113,792 B => 2 CTAs/SM
#define HS_OFF   0                          // hs  [32][132]
#define XS_OFF   (HS_OFF + 32*132)          // xss [32][260] (x tile in input stage, stride 62)
#define WS_OFF   (XS_OFF + 32*260)          // ws  [64][132]
#define TS_OFF   (WS_OFF + 64*132)          // ts  [32][132] pre-LN scratch
#define BC_OFF   (TS_OFF + 32*132)          // bcs [32][68]
#define DTB_OFF  (BC_OFF + 32*68)           // dtB [32][32]
#define YA_OFF   (DTB_OFF + 32*32)          // ya  [32]
#define SMEM_FLOATS (YA_OFF + 32)
#define SMEM_BYTES  (SMEM_FLOATS * 4)

// ---- 32x64 tile, K=128. Warp 16x16; thread 4 rows x 2 cols. Plain version.
DEVI void gemm32(const float* __restrict__ a, int lda, const float* __restrict__ w,
                 float vals[4][2], int row0, int col0) {
    ull acc[4][2];
    #pragma unroll
    for (int i = 0; i < 4; i++)
        #pragma unroll
        for (int j = 0; j < 2; j++) acc[i][j] = 0ull;
    #pragma unroll 4
    for (int k = 0; k < 128; k += 4) {
        ulonglong2 av[4], bv[2];
        #pragma unroll
        for (int i = 0; i < 4; i++) av[i] = *(const ulonglong2*)(a + (row0 + 4*i)*lda + k);
        #pragma unroll
        for (int j = 0; j < 2; j++) bv[j] = *(const ulonglong2*)(w + (col0 + 8*j)*132 + k);
        #pragma unroll
        for (int i = 0; i < 4; i++)
            #pragma unroll
            for (int j = 0; j < 2; j++) {
                fma2(acc[i][j], av[i].x, bv[j].x);
                fma2(acc[i][j], av[i].y, bv[j].y);
            }
    }
    #pragma unroll
    for (int i = 0; i < 4; i++)
        #pragma unroll
        for (int j = 0; j < 2; j++) vals[i][j] += psum(acc[i][j]);
}

// ---- same GEMM with 2 streaming state stores per k-step (64 total/thread).
// xrow: silu(x_ssm) slice (smem, broadcast reads). p: coalesced .cs float4 base.
DEVI void gemm32s(const float* __restrict__ a, int lda, const float* __restrict__ w,
                  float vals[4][2], int row0, int col0,
                  const float* __restrict__ xrow, float4 db, float* __restrict__ p) {
    ull acc[4][2];
    #pragma unroll
    for (int i = 0; i < 4; i++)
        #pragma unroll
        for (int j = 0; j < 2; j++) acc[i][j] = 0ull;
    #pragma unroll 4
    for (int k = 0; k < 128; k += 4) {
        ulonglong2 av[4], bv[2];
        #pragma unroll
        for (int i = 0; i < 4; i++) av[i] = *(const ulonglong2*)(a + (row0 + 4*i)*lda + k);
        #pragma unroll
        for (int j = 0; j < 2; j++) bv[j] = *(const ulonglong2*)(w + (col0 + 8*j)*132 + k);
        #pragma unroll
        for (int i = 0; i < 4; i++)
            #pragma unroll
            for (int j = 0; j < 2; j++) {
                fma2(acc[i][j], av[i].x, bv[j].x);
                fma2(acc[i][j], av[i].y, bv[j].y);
            }
        // interleaved state stores: d = k/2, k/2+1
        {
            int d = k >> 1;
            float xv0 = xrow[d], xv1 = xrow[d + 1];
            float4 v0; v0.x = xv0*db.x; v0.y = xv0*db.y; v0.z = xv0*db.z; v0.w = xv0*db.w;
            float4 v1; v1.x = xv1*db.x; v1.y = xv1*db.y; v1.z = xv1*db.z; v1.w = xv1*db.w;
            __stcs((float4*)p, v0);
            __stcs((float4*)(p + 32), v1);
            p += 64;
        }
    }
    #pragma unroll
    for (int i = 0; i < 4; i++)
        #pragma unroll
        for (int j = 0; j < 2; j++) vals[i][j] += psum(acc[i][j]);
}

// split weight-slab load (64 rows x 128 cols)
DEVI void ldg_ws(float4 v[8], const float* __restrict__ g, int gld) {
    #pragma unroll
    for (int t = 0; t < 8; t++) {
        int idx = threadIdx.x + t * NTHR;
        int r = idx >> 5, kq = idx & 31;
        v[t] = __ldg((const float4*)(g + r*gld + kq*4));
    }
}
DEVI void sts_ws(float* ws, const float4 v[8]) {
    #pragma unroll
    for (int t = 0; t < 8; t++) {
        int idx = threadIdx.x + t * NTHR;
        int r = idx >> 5, kq = idx & 31;
        *(float4*)(ws + r*132 + kq*4) = v[t];
    }
}

// per-row LayerNorm over 128 cols; warp w owns rows [4w, 4w+4).
DEVI void do_ln(float* hs, const float* src, int lds,
                const float* __restrict__ g, const float* __restrict__ b, bool addres) {
    int w = threadIdx.x >> 5, lane = threadIdx.x & 31;
    float4 gg = *(const float4*)(g + lane*4);
    float4 bb = *(const float4*)(b + lane*4);
    for (int r = w*4; r < w*4 + 4; r++) {
        float4 v = *(const float4*)(src + r*lds + lane*4);
        if (addres) {
            float4 h = *(const float4*)(hs + r*132 + lane*4);
            v.x += h.x; v.y += h.y; v.z += h.z; v.w += h.w;
        }
        float s = v.x + v.y + v.z + v.w;
        float q = v.x*v.x + v.y*v.y + v.z*v.z + v.w*v.w;
        #pragma unroll
        for (int o = 16; o > 0; o >>= 1) {
            s += __shfl_xor_sync(0xffffffffu, s, o);
            q += __shfl_xor_sync(0xffffffffu, q, o);
        }
        float m   = s * (1.f/128.f);
        float inv = rsqrtf(fmaxf(q * (1.f/128.f) - m*m, 0.f) + 1e-5f);
        float4 o4;
        o4.x = (v.x - m)*inv*gg.x + bb.x;
        o4.y = (v.y - m)*inv*gg.y + bb.y;
        o4.z = (v.z - m)*inv*gg.z + bb.z;
        o4.w = (v.w - m)*inv*gg.w + bb.w;
        *(float4*)(hs + r*132 + lane*4) = o4;
    }
}

__global__ void __launch_bounds__(NTHR, 2) fused_kernel(
    const float* __restrict__ x,      const float* __restrict__ w_in,
    const float* __restrict__ b_in,   const float* __restrict__ ln_in_g,
    const float* __restrict__ ln_in_b,
    const float* __restrict__ in_w0,  const float* __restrict__ Dp0,
    const float* __restrict__ out_w0, const float* __restrict__ ln_g0,
    const float* __restrict__ ln_b0,
    const float* __restrict__ in_w1,  const float* __restrict__ Dp1,
    const float* __restrict__ out_w1, const float* __restrict__ ln_g1,
    const float* __restrict__ ln_b1,
    const float* __restrict__ fn_g,   const float* __restrict__ fn_b,
    const float* __restrict__ sh_w1,  const float* __restrict__ sh_b1,
    const float* __restrict__ sh_w2,  const float* __restrict__ sh_b2,
    const float* __restrict__ k_w,    const float* __restrict__ k_b,
    const float* __restrict__ ki_w,   const float* __restrict__ ki_b,
    float* __restrict__ outp)
{
    extern __shared__ float sm[];
    float* hs   = sm + HS_OFF;
    float* xss  = sm + XS_OFF;
    float* ws   = sm + WS_OFF;
    float* ts   = sm + TS_OFF;
    float* bcs  = sm + BC_OFF;
    float* dtBs = sm + DTB_OFF;
    float* yav  = sm + YA_OFF;

    const int tid  = threadIdx.x;
    const int wid  = tid >> 5, lane = tid & 31;
    const int wr   = wid & 1,  wc2  = wid >> 1;      // warp grid 2x4
    const int lr   = lane >> 3, lc  = lane & 7;      // lane grid 4x8
    const int row0 = wr*16 + lr;
    const int col0 = wc2*16 + lc;
    const int rowbase = blockIdx.x * TB;
    const int r_st = tid >> 3, sq_st = tid & 7;      // state-store mapping

    // ============ input stage: h = LN(x @ w_in^T + b_in) ============
    for (int idx = tid; idx < 32*58; idx += NTHR) {
        int r = idx / 58, k = idx - r*58;
        xss[r*62 + k] = x[(size_t)(rowbase + r)*58 + k];
    }
    for (int idx = tid; idx < 128*58; idx += NTHR) {
        int r = idx / 58, k = idx - r*58;
        ws[r*62 + k] = w_in[idx];
    }
    __syncthreads();
    {
        ull acc[4][4];
        #pragma unroll
        for (int i = 0; i < 4; i++)
            #pragma unroll
            for (int j = 0; j < 4; j++) acc[i][j] = 0ull;
        #pragma unroll 1
        for (int k = 0; k < 58; k += 2) {
            ull a[4], b[4];
            #pragma unroll
            for (int i = 0; i < 4; i++) a[i] = *(const ull*)(xss + (row0 + 4*i)*62 + k);
            #pragma unroll
            for (int j = 0; j < 4; j++) b[j] = *(const ull*)(ws + (wc2*32 + lc + 8*j)*62 + k);
            #pragma unroll
            for (int i = 0; i < 4; i++)
                #pragma unroll
                for (int j = 0; j < 4; j++) fma2(acc[i][j], a[i], b[j]);
        }
        #pragma unroll
        for (int i = 0; i < 4; i++)
            #pragma unroll
            for (int j = 0; j < 4; j++) {
                int c = wc2*32 + lc + 8*j;
                ts[(row0 + 4*i)*132 + c] = psum(acc[i][j]) + __ldg(b_in + c);
            }
    }
    __syncthreads();
    do_ln(hs, ts, 132, ln_in_g, ln_in_b, false);
    __syncthreads();

    // load L0 B/C slab
    {
        float4 pf[8];
        ldg_ws(pf, in_w0 + 512*128, 128);
        sts_ws(ws, pf);
        __syncthreads();
    }

    // ============ two mamba layers ============
    const float* in_w_l[2]  = {in_w0, in_w1};
    const float* Dp_l[2]    = {Dp0, Dp1};
    const float* out_w_l[2] = {out_w0, out_w1};
    const float* g_l[2]     = {ln_g0, ln_g1};
    const float* b_l[2]     = {ln_b0, ln_b1};
    const ull    soff_l[2]  = {ST0_OFF, ST1_OFF};

    for (int L = 0; L < 2; L++) {
        const float* in_w  = in_w_l[L];
        const float* Dp    = Dp_l[L];
        const float* out_w = out_w_l[L];
        const ull    soff  = soff_l[L];
        const float* nxt_after = (L == 0) ? (in_w1 + 512*128) : sh_w1;
        // per-thread state-store base for this layer (row r_st, quad sq_st)
        float* stb = outp + soff + ((ull)(rowbase + r_st)*256ull)*32ull + (ull)(sq_st*4);

        // ---- B|C phase (proj cols 512..575) ----
        {
            float4 pf[8];
            ldg_ws(pf, in_w + 256*128, 128);           // prefetch xs0
            float vals[4][2] = {};
            gemm32(hs, 132, ws, vals, row0, col0);
            #pragma unroll
            for (int i = 0; i < 4; i++)
                #pragma unroll
                for (int j = 0; j < 2; j++)
                    bcs[(row0 + 4*i)*68 + col0 + 8*j] = vals[i][j];
            __syncthreads();
            sts_ws(ws, pf);
            __syncthreads();
        }

        // ---- per-row scalars: dt (col 576), bc = B·C, dtB, ya ----
        if (tid < 32) {
            const float* wdt = in_w + 576*128;
            float acc = 0.f;
            #pragma unroll 4
            for (int kk = 0; kk < 128; kk++) {
                int k = (kk + tid) & 127;
                acc += hs[tid*132 + k] * __ldg(wdt + k);
            }
            float dt = softpl(acc);
            float bc = 0.f;
            #pragma unroll
            for (int ss = 0; ss < 32; ss++) {
                int s = (ss + tid) & 31;
                float Bv = bcs[tid*68 + s];
                bc += Bv * bcs[tid*68 + 32 + s];
                dtBs[tid*32 + s] = dt * Bv;
            }
            yav[tid] = dt * bc;
        }

        // ---- x_ssm chunks (proj cols 256..511); sub>=1 carries store of sub-1 ----
        for (int sub = 0; sub < 4; sub++) {
            const float* nx = (sub < 3) ? (in_w + (256 + 64*(sub+1))*128) : in_w;
            float4 pf[8];
            ldg_ws(pf, nx, 128);
            float vals[4][2] = {};
            if (sub == 0) {
                gemm32(hs, 132, ws, vals, row0, col0);
            } else {
                float4 db = *(const float4*)(dtBs + r_st*32 + sq_st*4);
                gemm32s(hs, 132, ws, vals, row0, col0,
                        xss + r_st*260 + (sub-1)*64, db, stb + (ull)((sub-1)*64)*32ull);
            }
            #pragma unroll
            for (int i = 0; i < 4; i++)
                #pragma unroll
                for (int j = 0; j < 2; j++)
                    xss[(row0 + 4*i)*260 + sub*64 + col0 + 8*j] = siluf(vals[i][j]);
            __syncthreads();
            sts_ws(ws, pf);
            __syncthreads();
        }

        // ---- z chunks (proj cols 0..255); z0 carries store of xs3 ----
        for (int sub = 0; sub < 4; sub++) {
            const float* nx; int ngld;
            if (sub < 3) { nx = in_w + 64*(sub+1)*128; ngld = 128; }
            else         { nx = out_w;                 ngld = 256; }
            float4 pf[8];
            ldg_ws(pf, nx, ngld);
            float vals[4][2] = {};
            if (sub == 0) {
                float4 db = *(const float4*)(dtBs + r_st*32 + sq_st*4);
                gemm32s(hs, 132, ws, vals, row0, col0,
                        xss + r_st*260 + 192, db, stb + (ull)192*32ull);
            } else {
                gemm32(hs, 132, ws, vals, row0, col0);
            }
            #pragma unroll
            for (int i = 0; i < 4; i++)
                #pragma unroll
                for (int j = 0; j < 2; j++) {
                    int r = row0 + 4*i, c = sub*64 + col0 + 8*j;
                    float xv = xss[r*260 + c];
                    xss[r*260 + c] = siluf(vals[i][j]) * xv * (yav[r] + __ldg(Dp + c));
                }
            __syncthreads();
            sts_ws(ws, pf);
            __syncthreads();
        }

        // ---- out GEMM: ts = u @ out_w^T (128 cols, K=256, 2x2 slabs) ----
        for (int ch = 0; ch < 2; ch++) {
            float vals[4][2] = {};
            for (int kh = 0; kh < 2; kh++) {
                int sidx = ch*2 + kh + 1;
                const float* nx; int ngld;
                if (sidx < 4) { nx = out_w + (size_t)(sidx >> 1)*64*256 + (sidx & 1)*128; ngld = 256; }
                else          { nx = nxt_after; ngld = 128; }
                float4 pf[8];
                ldg_ws(pf, nx, ngld);
                gemm32(xss + kh*128, 260, ws, vals, row0, col0);
                __syncthreads();
                sts_ws(ws, pf);
                __syncthreads();
            }
            #pragma unroll
            for (int i = 0; i < 4; i++)
                #pragma unroll
                for (int j = 0; j < 2; j++)
                    ts[(row0 + 4*i)*132 + ch*64 + col0 + 8*j] = vals[i][j];
        }
        __syncthreads();
        do_ln(hs, ts, 132, g_l[L], b_l[L], true);
        __syncthreads();
    }

    // ============ final LN + heads ============
    do_ln(hs, hs, 132, fn_g, fn_b, false);
    __syncthreads();

    // t1 = gelu(h @ sh_w1^T + sh_b1) -> bcs (stride 68); sh_w1 already in ws
    {
        float vals[4][2] = {};
        gemm32(hs, 132, ws, vals, row0, col0);
        #pragma unroll
        for (int i = 0; i < 4; i++)
            #pragma unroll
            for (int j = 0; j < 2; j++) {
                int c = col0 + 8*j;
                bcs[(row0 + 4*i)*68 + c] = geluf(vals[i][j] + __ldg(sh_b1 + c));
            }
    }
    __syncthreads();

    // scaling = softplus(t1 @ sh_w2^T + sh_b2)  (9 cols)
    for (int idx = tid; idx < 32*9; idx += NTHR) {
        int r = idx / 9, c = idx - r*9;
        float acc = __ldg(sh_b2 + c);
        #pragma unroll 4
        for (int ss = 0; ss < 64; ss++) {
            int s = (ss + tid) & 63;
            acc += bcs[r*68 + s] * __ldg(sh_w2 + c*64 + s);
        }
        outp[SCAL_OFF + (ull)(rowbase + r)*9ull + c] = softpl(acc);
    }

    // K, K_internal (per-row dots over h)
    if (tid < 32) {
        float a0 = 0.f, a1 = 0.f;
        #pragma unroll 4
        for (int kk = 0; kk < 128; kk++) {
            int k = (kk + tid) & 127;
            float hv = hs[tid*132 + k];
            a0 += hv * __ldg(k_w + k);
            a1 += hv * __ldg(ki_w + k);
        }
        outp[K_OFF  + (ull)(rowbase + tid)] = sigm(a0 + __ldg(k_b));
        outp[KI_OFF + (ull)(rowbase + tid)] = sigm(a1 + __ldg(ki_b));
    }
}

extern "C" void kernel_launch(void* const* d_in, const int* in_sizes, int n_in,
                              void* d_out, int out_size) {
    (void)in_sizes; (void)n_in; (void)out_size;
    cudaFuncSetAttribute(fused_kernel, cudaFuncAttributeMaxDynamicSharedMemorySize, SMEM_BYTES);
    fused_kernel<<<NBLK, NTHR, SMEM_BYTES>>>(
        (const float*)d_in[0],  (const float*)d_in[1],  (const float*)d_in[2],
        (const float*)d_in[3],  (const float*)d_in[4],
        (const float*)d_in[5],  (const float*)d_in[7],  (const float*)d_in[8],
        (const float*)d_in[9],  (const float*)d_in[10],
        (const float*)d_in[11], (const float*)d_in[13], (const float*)d_in[14],
        (const float*)d_in[15], (const float*)d_in[16],
        (const float*)d_in[17], (const float*)d_in[18],
        (const float*)d_in[19], (const float*)d_in[20],
        (const float*)d_in[21], (const float*)d_in[22],
        (const float*)d_in[23], (const float*)d_in[24],
        (const float*)d_in[25], (const float*)d_in[26],
        (float*)d_out);
}